// round 1
// baseline (speedup 1.0000x reference)
#include <cuda_runtime.h>
#include <math_constants.h>

#define BB 64
#define TT 2048
#define HH 512
#define UNITS 128
#define SPLITS 8
#define ROWS_PER_SPLIT (TT / SPLITS) // 256

// Scratch (no allocations allowed in kernel_launch)
__device__ float g_v[BB * HH];            // v[b,h] = sum_k W_score[h,k] * h_t[b,k]
__device__ float g_m[BB * SPLITS];        // split-softmax partial max
__device__ float g_l[BB * SPLITS];        // split-softmax partial sum
__device__ float g_c[BB * SPLITS * HH];   // split partial context (unnormalized)

// ---------------------------------------------------------------------------
// k1: v[b,:] = W_score @ h_t[b,:]   (h_t = hidden[b, T-1, :])
// grid (B, 4): block handles 128 rows of W_score for one b.
// Each warp does one row dot (contiguous 2KB, coalesced), 16 rows/warp.
// ---------------------------------------------------------------------------
__global__ void __launch_bounds__(256) k1_vscore(const float* __restrict__ hidden,
                                                 const float* __restrict__ Wscore) {
    const int b = blockIdx.x;
    const int hc = blockIdx.y;
    __shared__ float ht[HH];
    const float* htg = hidden + ((size_t)b * TT + (TT - 1)) * HH;
    for (int i = threadIdx.x; i < HH; i += blockDim.x) ht[i] = htg[i];
    __syncthreads();

    const int warp = threadIdx.x >> 5;
    const int lane = threadIdx.x & 31;
    const float4* ht4 = (const float4*)ht;

    for (int r = warp; r < 128; r += 8) {
        const int h = hc * 128 + r;
        const float4* wrow = (const float4*)(Wscore + (size_t)h * HH);
        float acc = 0.f;
        #pragma unroll
        for (int i = 0; i < 4; i++) {
            float4 w = wrow[i * 32 + lane];
            float4 x = ht4[i * 32 + lane];
            acc += w.x * x.x + w.y * x.y + w.z * x.z + w.w * x.w;
        }
        #pragma unroll
        for (int o = 16; o; o >>= 1) acc += __shfl_xor_sync(0xFFFFFFFFu, acc, o);
        if (lane == 0) g_v[b * HH + h] = acc;
    }
}

// ---------------------------------------------------------------------------
// k2: single streaming pass over hidden_states with online softmax.
// grid (SPLITS, B), 256 threads (8 warps). Warp w handles rows t0+w, t0+w+8, ...
// Per row: s = hidden[b,t,:].v ; online update of (m, l, c[16 floats/lane]).
// CTA-level combine across 8 warps -> one split partial in g_{m,l,c}.
// ---------------------------------------------------------------------------
__global__ void __launch_bounds__(256, 2) k2_flash(const float* __restrict__ hidden) {
    const int s  = blockIdx.x;
    const int b  = blockIdx.y;
    const int warp = threadIdx.x >> 5;
    const int lane = threadIdx.x & 31;

    // v for this batch, register-resident (16 floats/lane)
    const float4* v4g = (const float4*)(g_v + b * HH);
    float4 v4[4];
    #pragma unroll
    for (int i = 0; i < 4; i++) v4[i] = v4g[i * 32 + lane];

    float m = -CUDART_INF_F;
    float l = 0.f;
    float4 c[4];
    #pragma unroll
    for (int i = 0; i < 4; i++) c[i] = make_float4(0.f, 0.f, 0.f, 0.f);

    const int t0 = s * ROWS_PER_SPLIT;
    for (int r = warp; r < ROWS_PER_SPLIT; r += 8) {
        const float4* row = (const float4*)(hidden + ((size_t)b * TT + t0 + r) * HH);
        float4 h4[4];
        float acc = 0.f;
        #pragma unroll
        for (int i = 0; i < 4; i++) {
            h4[i] = row[i * 32 + lane];
            acc += h4[i].x * v4[i].x + h4[i].y * v4[i].y
                 + h4[i].z * v4[i].z + h4[i].w * v4[i].w;
        }
        #pragma unroll
        for (int o = 16; o; o >>= 1) acc += __shfl_xor_sync(0xFFFFFFFFu, acc, o);
        // acc (score) is warp-uniform here -> branch is warp-uniform.
        if (acc <= m) {
            const float p = __expf(acc - m);
            l += p;
            #pragma unroll
            for (int i = 0; i < 4; i++) {
                c[i].x += p * h4[i].x; c[i].y += p * h4[i].y;
                c[i].z += p * h4[i].z; c[i].w += p * h4[i].w;
            }
        } else {
            const float corr = __expf(m - acc);  // exp(-inf)=0 handles first row
            m = acc;
            l = l * corr + 1.f;                  // p = 1 for the new max row
            #pragma unroll
            for (int i = 0; i < 4; i++) {
                c[i].x = c[i].x * corr + h4[i].x; c[i].y = c[i].y * corr + h4[i].y;
                c[i].z = c[i].z * corr + h4[i].z; c[i].w = c[i].w * corr + h4[i].w;
            }
        }
    }

    // CTA combine across 8 warps
    __shared__ float s_c[8][HH];   // 16 KB
    __shared__ float s_m[8], s_l[8];
    float4* sc4 = (float4*)s_c[warp];
    #pragma unroll
    for (int i = 0; i < 4; i++) sc4[i * 32 + lane] = c[i];
    if (lane == 0) { s_m[warp] = m; s_l[warp] = l; }
    __syncthreads();

    float M = s_m[0];
    #pragma unroll
    for (int w = 1; w < 8; w++) M = fmaxf(M, s_m[w]);

    float wexp[8];
    #pragma unroll
    for (int w = 0; w < 8; w++) wexp[w] = __expf(s_m[w] - M);

    const int idx = b * SPLITS + s;
    for (int col = threadIdx.x; col < HH; col += 256) {
        float acc = 0.f;
        #pragma unroll
        for (int w = 0; w < 8; w++) acc += s_c[w][col] * wexp[w];
        g_c[(size_t)idx * HH + col] = acc;
    }
    if (threadIdx.x == 0) {
        float L = 0.f;
        #pragma unroll
        for (int w = 0; w < 8; w++) L += s_l[w] * wexp[w];
        g_m[idx] = M;
        g_l[idx] = L;
    }
}

// ---------------------------------------------------------------------------
// k3: combine split partials -> context[b,:], then
//     out[b,:] = tanh(concat(context, h_t) @ W_out)
// grid (B), 256 threads. W_out columns accessed coalesced; matrix is
// L2-resident (512 KB).
// ---------------------------------------------------------------------------
__global__ void __launch_bounds__(256) k3_out(const float* __restrict__ hidden,
                                              const float* __restrict__ Wout,
                                              float* __restrict__ out) {
    const int b = blockIdx.x;
    __shared__ float ctx[HH];
    __shared__ float ht[HH];
    __shared__ float part[UNITS];

    float M = -CUDART_INF_F;
    #pragma unroll
    for (int s2 = 0; s2 < SPLITS; s2++) M = fmaxf(M, g_m[b * SPLITS + s2]);
    float wexp[SPLITS];
    float L = 0.f;
    #pragma unroll
    for (int s2 = 0; s2 < SPLITS; s2++) {
        wexp[s2] = __expf(g_m[b * SPLITS + s2] - M);
        L += g_l[b * SPLITS + s2] * wexp[s2];
    }
    const float invL = 1.f / L;

    const float* htg = hidden + ((size_t)b * TT + (TT - 1)) * HH;
    for (int col = threadIdx.x; col < HH; col += 256) {
        float acc = 0.f;
        #pragma unroll
        for (int s2 = 0; s2 < SPLITS; s2++)
            acc += g_c[((size_t)b * SPLITS + s2) * HH + col] * wexp[s2];
        ctx[col] = acc * invL;
        ht[col] = htg[col];
    }
    __syncthreads();

    float acc = 0.f;
    if (threadIdx.x < 128) {
        const int u = threadIdx.x;
        for (int h = 0; h < HH; h++) acc += ctx[h] * Wout[h * UNITS + u];
    } else {
        const int u = threadIdx.x - 128;
        float a2 = 0.f;
        for (int h = 0; h < HH; h++) a2 += ht[h] * Wout[(HH + h) * UNITS + u];
        part[u] = a2;
    }
    __syncthreads();
    if (threadIdx.x < 128)
        out[b * UNITS + threadIdx.x] = tanhf(acc + part[threadIdx.x]);
}

extern "C" void kernel_launch(void* const* d_in, const int* in_sizes, int n_in,
                              void* d_out, int out_size) {
    const float* hidden = (const float*)d_in[0];   // [B, T, H]
    const float* Wscore = (const float*)d_in[1];   // [H, H]
    const float* Wout   = (const float*)d_in[2];   // [2H, UNITS]
    float* out = (float*)d_out;                    // [B, UNITS]

    k1_vscore<<<dim3(BB, 4), 256>>>(hidden, Wscore);
    k2_flash<<<dim3(SPLITS, BB), 256>>>(hidden);
    k3_out<<<BB, 256>>>(hidden, Wout, out);
}

// round 2
// speedup vs baseline: 1.4092x; 1.4092x over previous
#include <cuda_runtime.h>
#include <math_constants.h>

#define BB 64
#define TT 2048
#define HH 512
#define UNITS 128
#define SPLITS 16
#define ROWS_PER_SPLIT (TT / SPLITS) // 128

// Scratch (no allocations allowed in kernel_launch)
__device__ float g_v[BB * HH];            // v[b,h] = sum_k W_score[h,k] * h_t[b,k]
__device__ float g_m[BB * SPLITS];        // split-softmax partial max
__device__ float g_l[BB * SPLITS];        // split-softmax partial sum
__device__ float g_c[BB * SPLITS * HH];   // split partial context (unnormalized)

// ---------------------------------------------------------------------------
// k1: v[b,:] = W_score @ h_t[b,:]  for all b, tiled 8 batches x 64 h-rows.
// grid (8, 8): block = (b-tile of 8, h-tile of 64). W row loaded once per
// warp-row, reused for 8 batches -> 8 independent reduce chains pipeline.
// ---------------------------------------------------------------------------
__global__ void __launch_bounds__(256) k1_vscore(const float* __restrict__ hidden,
                                                 const float* __restrict__ Wscore) {
    const int b0 = blockIdx.x * 8;
    const int h0 = blockIdx.y * 64;
    __shared__ float ht[8][HH];   // 16 KB

    for (int idx = threadIdx.x; idx < 8 * HH; idx += 256) {
        const int bl = idx >> 9;          // /512
        const int k  = idx & (HH - 1);
        ht[bl][k] = hidden[((size_t)(b0 + bl) * TT + (TT - 1)) * HH + k];
    }
    __syncthreads();

    const int warp = threadIdx.x >> 5;
    const int lane = threadIdx.x & 31;

    for (int hr = warp; hr < 64; hr += 8) {
        const int h = h0 + hr;
        const float4* w4 = (const float4*)(Wscore + (size_t)h * HH);
        float acc[8];
        #pragma unroll
        for (int bl = 0; bl < 8; bl++) acc[bl] = 0.f;

        #pragma unroll
        for (int i = 0; i < 4; i++) {
            float4 w = w4[i * 32 + lane];
            #pragma unroll
            for (int bl = 0; bl < 8; bl++) {
                float4 x = ((const float4*)ht[bl])[i * 32 + lane];
                acc[bl] += w.x * x.x + w.y * x.y + w.z * x.z + w.w * x.w;
            }
        }
        #pragma unroll
        for (int o = 16; o; o >>= 1) {
            #pragma unroll
            for (int bl = 0; bl < 8; bl++)
                acc[bl] += __shfl_xor_sync(0xFFFFFFFFu, acc[bl], o);
        }
        if (lane == 0) {
            #pragma unroll
            for (int bl = 0; bl < 8; bl++)
                g_v[(b0 + bl) * HH + h] = acc[bl];
        }
    }
}

// ---------------------------------------------------------------------------
// k2: streaming pass over hidden with online softmax, 2 rows / warp / iter.
// grid (SPLITS, B), 256 threads (8 warps). Two independent dot+reduce chains
// per iteration interleave; 8 LDG.128 in flight per warp.
// ---------------------------------------------------------------------------
__global__ void __launch_bounds__(256, 2) k2_flash(const float* __restrict__ hidden) {
    const int s  = blockIdx.x;
    const int b  = blockIdx.y;
    const int warp = threadIdx.x >> 5;
    const int lane = threadIdx.x & 31;

    const float4* v4g = (const float4*)(g_v + b * HH);
    float4 v4[4];
    #pragma unroll
    for (int i = 0; i < 4; i++) v4[i] = v4g[i * 32 + lane];

    float m = -CUDART_INF_F;
    float l = 0.f;
    float4 c[4];
    #pragma unroll
    for (int i = 0; i < 4; i++) c[i] = make_float4(0.f, 0.f, 0.f, 0.f);

    const size_t base = ((size_t)b * TT + s * ROWS_PER_SPLIT) * HH;

    #pragma unroll 1
    for (int it = 0; it < ROWS_PER_SPLIT / 16; it++) {
        const int r0 = (it * 8 + warp) * 2;
        const float4* rowA = (const float4*)(hidden + base + (size_t)r0 * HH);
        const float4* rowB = (const float4*)(hidden + base + (size_t)(r0 + 1) * HH);

        float4 a4[4], b4[4];
        float sa = 0.f, sb = 0.f;
        #pragma unroll
        for (int i = 0; i < 4; i++) {
            a4[i] = __ldcs(rowA + i * 32 + lane);
            b4[i] = __ldcs(rowB + i * 32 + lane);
        }
        #pragma unroll
        for (int i = 0; i < 4; i++) {
            sa += a4[i].x * v4[i].x + a4[i].y * v4[i].y
                + a4[i].z * v4[i].z + a4[i].w * v4[i].w;
            sb += b4[i].x * v4[i].x + b4[i].y * v4[i].y
                + b4[i].z * v4[i].z + b4[i].w * v4[i].w;
        }
        #pragma unroll
        for (int o = 16; o; o >>= 1) {
            sa += __shfl_xor_sync(0xFFFFFFFFu, sa, o);
            sb += __shfl_xor_sync(0xFFFFFFFFu, sb, o);
        }

        const float mt = fmaxf(sa, sb);
        if (mt <= m) {   // warp-uniform branch
            const float pa = __expf(sa - m);
            const float pb = __expf(sb - m);
            l += pa + pb;
            #pragma unroll
            for (int i = 0; i < 4; i++) {
                c[i].x += pa * a4[i].x + pb * b4[i].x;
                c[i].y += pa * a4[i].y + pb * b4[i].y;
                c[i].z += pa * a4[i].z + pb * b4[i].z;
                c[i].w += pa * a4[i].w + pb * b4[i].w;
            }
        } else {
            const float corr = __expf(m - mt);  // exp(-inf)=0 on first iter
            const float pa = __expf(sa - mt);
            const float pb = __expf(sb - mt);
            m = mt;
            l = l * corr + pa + pb;
            #pragma unroll
            for (int i = 0; i < 4; i++) {
                c[i].x = c[i].x * corr + pa * a4[i].x + pb * b4[i].x;
                c[i].y = c[i].y * corr + pa * a4[i].y + pb * b4[i].y;
                c[i].z = c[i].z * corr + pa * a4[i].z + pb * b4[i].z;
                c[i].w = c[i].w * corr + pa * a4[i].w + pb * b4[i].w;
            }
        }
    }

    // CTA combine across 8 warps
    __shared__ float s_c[8][HH];   // 16 KB
    __shared__ float s_m[8], s_l[8];
    float4* sc4 = (float4*)s_c[warp];
    #pragma unroll
    for (int i = 0; i < 4; i++) sc4[i * 32 + lane] = c[i];
    if (lane == 0) { s_m[warp] = m; s_l[warp] = l; }
    __syncthreads();

    float M = s_m[0];
    #pragma unroll
    for (int w = 1; w < 8; w++) M = fmaxf(M, s_m[w]);

    float wexp[8];
    #pragma unroll
    for (int w = 0; w < 8; w++) wexp[w] = __expf(s_m[w] - M);

    const int idx = b * SPLITS + s;
    for (int col = threadIdx.x; col < HH; col += 256) {
        float acc = 0.f;
        #pragma unroll
        for (int w = 0; w < 8; w++) acc += s_c[w][col] * wexp[w];
        g_c[(size_t)idx * HH + col] = acc;
    }
    if (threadIdx.x == 0) {
        float L = 0.f;
        #pragma unroll
        for (int w = 0; w < 8; w++) L += s_l[w] * wexp[w];
        g_m[idx] = M;
        g_l[idx] = L;
    }
}

// ---------------------------------------------------------------------------
// k3: combine split partials -> context[b,:], then
//     out[b,:] = tanh(concat(context, h_t) @ W_out)
// ---------------------------------------------------------------------------
__global__ void __launch_bounds__(256) k3_out(const float* __restrict__ hidden,
                                              const float* __restrict__ Wout,
                                              float* __restrict__ out) {
    const int b = blockIdx.x;
    __shared__ float ctx[HH];
    __shared__ float ht[HH];
    __shared__ float part[UNITS];

    float M = -CUDART_INF_F;
    #pragma unroll
    for (int s2 = 0; s2 < SPLITS; s2++) M = fmaxf(M, g_m[b * SPLITS + s2]);
    float L = 0.f;
    __shared__ float s_wexp[SPLITS];
    for (int s2 = threadIdx.x; s2 < SPLITS; s2 += 256)
        s_wexp[s2] = __expf(g_m[b * SPLITS + s2] - M);
    __syncthreads();
    #pragma unroll
    for (int s2 = 0; s2 < SPLITS; s2++) L += g_l[b * SPLITS + s2] * s_wexp[s2];
    const float invL = 1.f / L;

    const float* htg = hidden + ((size_t)b * TT + (TT - 1)) * HH;
    for (int col = threadIdx.x; col < HH; col += 256) {
        float acc = 0.f;
        #pragma unroll
        for (int s2 = 0; s2 < SPLITS; s2++)
            acc += g_c[((size_t)b * SPLITS + s2) * HH + col] * s_wexp[s2];
        ctx[col] = acc * invL;
        ht[col] = htg[col];
    }
    __syncthreads();

    float acc0 = 0.f, acc1 = 0.f;
    if (threadIdx.x < 128) {
        const int u = threadIdx.x;
        #pragma unroll 8
        for (int h = 0; h < HH; h += 2) {
            acc0 += ctx[h]     * Wout[(size_t)h * UNITS + u];
            acc1 += ctx[h + 1] * Wout[(size_t)(h + 1) * UNITS + u];
        }
    } else {
        const int u = threadIdx.x - 128;
        #pragma unroll 8
        for (int h = 0; h < HH; h += 2) {
            acc0 += ht[h]     * Wout[(size_t)(HH + h) * UNITS + u];
            acc1 += ht[h + 1] * Wout[(size_t)(HH + h + 1) * UNITS + u];
        }
        part[u] = acc0 + acc1;
    }
    __syncthreads();
    if (threadIdx.x < 128)
        out[b * UNITS + threadIdx.x] = tanhf(acc0 + acc1 + part[threadIdx.x]);
}

extern "C" void kernel_launch(void* const* d_in, const int* in_sizes, int n_in,
                              void* d_out, int out_size) {
    const float* hidden = (const float*)d_in[0];   // [B, T, H]
    const float* Wscore = (const float*)d_in[1];   // [H, H]
    const float* Wout   = (const float*)d_in[2];   // [2H, UNITS]
    float* out = (float*)d_out;                    // [B, UNITS]

    k1_vscore<<<dim3(8, 8), 256>>>(hidden, Wscore);
    k2_flash<<<dim3(SPLITS, BB), 256>>>(hidden);
    k3_out<<<BB, 256>>>(hidden, Wout, out);
}